// round 2
// baseline (speedup 1.0000x reference)
#include <cuda_runtime.h>
#include <math.h>

#define NL 24
#define NHD 16
#define HD 64
#define DM 1024
#define FF 4096
#define VOC 8194
#define TPAST 2047
#define TKV 2048
#define NB 148
#define NT 1024
#define KS_ELEMS (NL*NHD*HD*TKV)   /* 50331648 */

// ---------------- persistent scratch (device globals; no allocations) ----------------
__device__ float g_hbuf[2][DM];          // residual stream ping-pong
__device__ float g_qkv[3*DM];            // q | k_new | v_new (bias-initialized, atomics)
__device__ float g_h2[DM];               // h + attn_out + bo   (atomics)
__device__ float g_part[NHD*8*66];       // per (head,chunk): m, sumexp, acc[64]
__device__ unsigned g_count = 0;
__device__ volatile unsigned g_sense = 0;
__device__ unsigned long long g_best = 0ull;

__device__ __forceinline__ void gbar() {
    __syncthreads();
    if (threadIdx.x == 0) {
        __threadfence();
        unsigned cur = g_sense;
        if (atomicAdd(&g_count, 1u) == NB - 1u) {
            g_count = 0u;
            __threadfence();
            g_sense = cur + 1u;
        } else {
            while (g_sense == cur) __nanosleep(64);
        }
        __threadfence();
    }
    __syncthreads();
}

__device__ __forceinline__ float gelu_tanh(float x) {
    float x3 = x * x * x;
    float t = tanhf(0.7978845608028654f * (x + 0.044715f * x3));
    return 0.5f * x * (1.0f + t);
}

// LayerNorm of a 1024-vector: loads vec (L2-coherent), computes stats via block
// reduction, writes normalized*g+b into sx. rs/rq are 1024-float scratch each.
__device__ __forceinline__ void ln_vec(const float* __restrict__ vec,
                                       const float* __restrict__ gw,
                                       const float* __restrict__ bw,
                                       float* sx, float* rs, float* rq, int tid) {
    float v = __ldcg(&vec[tid]);
    rs[tid] = v; rq[tid] = v * v;
    for (int s = 512; s > 0; s >>= 1) {
        __syncthreads();
        if (tid < s) { rs[tid] += rs[tid + s]; rq[tid] += rq[tid + s]; }
    }
    __syncthreads();
    float mean = rs[0] * (1.0f / DM);
    float var  = rq[0] * (1.0f / DM) - mean * mean;
    float rstd = rsqrtf(var + 1e-5f);
    __syncthreads();           // everyone has read rs[0]/rq[0]; scratch reusable
    sx[tid] = (v - mean) * rstd * __ldg(&gw[tid]) + __ldg(&bw[tid]);
    __syncthreads();
}

__global__ void __launch_bounds__(NT, 1) tts_decode_kernel(
    const float* __restrict__ past_k, const float* __restrict__ past_v,
    const float* __restrict__ hidden, const float* __restrict__ logits_scale,
    const float* __restrict__ mask_scale,
    const float* __restrict__ ln1_g, const float* __restrict__ ln1_b,
    const float* __restrict__ Wq, const float* __restrict__ bq,
    const float* __restrict__ Wk, const float* __restrict__ bk,
    const float* __restrict__ Wv, const float* __restrict__ bv,
    const float* __restrict__ Wo, const float* __restrict__ bo,
    const float* __restrict__ ln2_g, const float* __restrict__ ln2_b,
    const float* __restrict__ Wfc, const float* __restrict__ bfc,
    const float* __restrict__ Wmp, const float* __restrict__ bmp,
    const float* __restrict__ lnf_g, const float* __restrict__ lnf_b,
    const float* __restrict__ lm_w,
    float* __restrict__ out)
{
    __shared__ float sm[3144];   // region-multiplexed scratch

    const int tid = threadIdx.x;
    const int bid = blockIdx.x;
    const float mskc = -128.0f * __ldg(&mask_scale[0]);

    // ---------------- init ----------------
    if (bid == 0) {
        g_hbuf[0][tid] = __ldg(&hidden[tid]);
    } else if (bid >= 1 && bid <= 3) {
        int mat = bid - 1;
        const float* bb = (mat == 0) ? bq : ((mat == 1) ? bk : bv);
        g_qkv[mat * DM + tid] = __ldg(&bb[tid]);     // layer 0 bias
    }
    gbar();

    for (int l = 0; l < NL; l++) {
        const int p = l & 1;
        const float* h_in  = g_hbuf[p];
        float* h_next = g_hbuf[p ^ 1];

        // ============ Stage A: QKV  (144 blocks: 3 mats x 16 heads x 3 d-chunks) ============
        if (bid < 144) {
            ln_vec(h_in, ln1_g + l * DM, ln1_b + l * DM, sm, sm + 1024, sm + 2048, tid);
            int mat = bid % 3;
            int rest = bid / 3;
            int h = rest % NHD;
            int chunk = rest / NHD;               // 0..2
            const float* W = ((mat == 0) ? Wq : ((mat == 1) ? Wk : Wv))
                             + (size_t)l * NHD * DM * HD + (size_t)h * DM * HD;
            int d0   = (chunk == 0) ? 0 : (342 + 341 * (chunk - 1));
            int dend = d0 + ((chunk == 0) ? 342 : 341);
            int e = tid & 63, dg = tid >> 6;      // 64 cols x 16 d-groups
            float acc = 0.0f;
            for (int d = d0 + dg; d < dend; d += 16)
                acc += sm[d] * __ldg(&W[(size_t)d * HD + e]);
            float* sacc = sm + 1024;
            sacc[dg * 64 + e] = acc;
            for (int s = 8; s > 0; s >>= 1) {
                __syncthreads();
                if (dg < s) sacc[dg * 64 + e] += sacc[(dg + s) * 64 + e];
            }
            __syncthreads();
            if (dg == 0) atomicAdd(&g_qkv[mat * DM + h * HD + e], sacc[e]);
        }
        gbar();

        // ============ Stage B: attention chunks (128 blocks) + g_h2 init ============
        if (bid < 128) {
            int h = bid >> 3, c = bid & 7;
            int t0 = c * 256;
            if (tid < 64) sm[tid] = __ldcg(&g_qkv[h * HD + tid]);   // q
            __syncthreads();
            float* ssc  = sm + 64;     // [4][256]
            float* ss   = sm + 1088;   // scores -> probs [256]
            float* rr   = sm + 1344;   // reduce [256]
            float* sacc = sm + 1600;   // [16][64]

            int t = tid & 255, eg = tid >> 8;
            int tg = t0 + t;
            size_t kbase  = ((size_t)(l * NHD + h) * HD) * TPAST;
            size_t okbase = ((size_t)(l * NHD + h) * HD) * TKV;
            float part = 0.0f;
            #pragma unroll 4
            for (int j = 0; j < 16; j++) {
                int e = eg * 16 + j;
                float kv;
                if (tg < TPAST) kv = __ldg(&past_k[kbase + (size_t)e * TPAST + tg]);
                else            kv = __ldcg(&g_qkv[DM + h * HD + e]);
                out[okbase + (size_t)e * TKV + tg] = kv;            // fused k copy
                part += sm[e] * kv;
            }
            ssc[eg * 256 + t] = part;
            __syncthreads();
            if (tid < 256) {
                float sc = ssc[t] + ssc[256 + t] + ssc[512 + t] + ssc[768 + t];
                if (tg > 0) sc += mskc;
                ss[t] = sc;
                rr[t] = sc;
            }
            for (int s = 128; s > 0; s >>= 1) {
                __syncthreads();
                if (tid < s) rr[tid] = fmaxf(rr[tid], rr[tid + s]);
            }
            __syncthreads();
            float m = rr[0];
            __syncthreads();
            if (tid < 256) { float pe = __expf(ss[t] - m); ss[t] = pe; rr[t] = pe; }
            for (int s = 128; s > 0; s >>= 1) {
                __syncthreads();
                if (tid < s) rr[tid] += rr[tid + s];
            }
            __syncthreads();
            float se = rr[0];

            int e = tid & 63, tgr = tid >> 6;     // 64 cols x 16 t-groups
            size_t vbase  = ((size_t)(l * NHD + h) * TPAST) * HD;
            size_t ovbase = (size_t)KS_ELEMS + ((size_t)(l * NHD + h) * TKV) * HD;
            float acc = 0.0f;
            #pragma unroll 4
            for (int j = 0; j < 16; j++) {
                int tt  = tgr * 16 + j;
                int tgl = t0 + tt;
                float vv;
                if (tgl < TPAST) vv = __ldg(&past_v[vbase + (size_t)tgl * HD + e]);
                else             vv = __ldcg(&g_qkv[2 * DM + h * HD + e]);
                out[ovbase + (size_t)tgl * HD + e] = vv;            // fused v copy
                acc += ss[tt] * vv;
            }
            sacc[tgr * 64 + e] = acc;
            for (int s = 8; s > 0; s >>= 1) {
                __syncthreads();
                if (tgr < s) sacc[tgr * 64 + e] += sacc[(tgr + s) * 64 + e];
            }
            __syncthreads();
            float* gp = &g_part[(h * 8 + c) * 66];
            if (tid == 0) { gp[0] = m; gp[1] = se; }
            if (tid < 64) gp[2 + tid] = sacc[tid];
        } else if (bid == 128) {
            g_h2[tid] = __ldg(&bo[l * DM + tid]);
        }
        gbar();

        // ============ Stage C: softmax combine + c_proj (128 blocks) + inits ============
        if (bid < 128) {
            int r0 = bid * 8;                 // rows (h*64+e) .. +7, single head
            int h = r0 >> 6, e0 = r0 & 63;
            float* sa = sm + 3072;            // attn[8]
            if (tid < 8) {
                float M = -1e30f;
                for (int c2 = 0; c2 < 8; c2++)
                    M = fmaxf(M, __ldcg(&g_part[(h * 8 + c2) * 66]));
                float den = 0.0f, num = 0.0f;
                for (int c2 = 0; c2 < 8; c2++) {
                    const float* gp = &g_part[(h * 8 + c2) * 66];
                    float w = __expf(__ldcg(&gp[0]) - M);
                    den += w * __ldcg(&gp[1]);
                    num += w * __ldcg(&gp[2 + e0 + tid]);
                }
                sa[tid] = num / den;
            }
            __syncthreads();
            const float* Wb = Wo + (size_t)l * DM * DM + (size_t)r0 * DM;
            float acc = 0.0f;
            #pragma unroll
            for (int j = 0; j < 8; j++)
                acc += sa[j] * __ldg(&Wb[(size_t)j * DM + tid]);
            atomicAdd(&g_h2[tid], acc);
        } else if (bid == 128) {
            atomicAdd(&g_h2[tid], __ldcg(&h_in[tid]));          // residual
        } else if (bid == 129) {
            h_next[tid] = __ldg(&bmp[l * DM + tid]);            // seed next residual
        } else if (bid >= 130 && bid < 133 && (l + 1) < NL) {
            int mat = bid - 130;
            const float* bb = (mat == 0) ? bq : ((mat == 1) ? bk : bv);
            g_qkv[mat * DM + tid] = __ldg(&bb[(l + 1) * DM + tid]);   // next-layer bias
        }
        gbar();

        // ============ Stage DE: fused MLP (128 blocks, 32 FF cols each) ============
        if (bid < 128) {
            ln_vec(g_h2, ln2_g + l * DM, ln2_b + l * DM, sm, sm + 1024, sm + 2048, tid);
            int f = tid & 31, dg = tid >> 5;           // 32 cols x 32 d-groups
            const float* Wf = Wfc + (size_t)l * DM * FF + (size_t)bid * 32;
            float acc = 0.0f;
            for (int d = dg; d < DM; d += 32)
                acc += sm[d] * __ldg(&Wf[(size_t)d * FF + f]);
            float* s32 = sm + 1024;                    // [32][33]
            s32[dg * 33 + f] = acc;
            __syncthreads();
            float* sy = sm + 2112;                     // gelu'd [32]
            if (tid < 32) {
                float y = __ldg(&bfc[l * FF + bid * 32 + tid]);
                for (int d2 = 0; d2 < 32; d2++) y += s32[d2 * 33 + tid];
                sy[tid] = gelu_tanh(y);
            }
            __syncthreads();
            const float* Wm = Wmp + (size_t)l * FF * DM + (size_t)(bid * 32) * DM;
            float acc2 = 0.0f;
            #pragma unroll 8
            for (int j = 0; j < 32; j++)
                acc2 += sy[j] * __ldg(&Wm[(size_t)j * DM + tid]);
            atomicAdd(&h_next[tid], acc2);
        } else if (bid == 128) {
            atomicAdd(&h_next[tid], __ldcg(&g_h2[tid]));        // residual
        }
        gbar();
    }

    // ============ Stage F: final LN + logits + argmax (129 blocks x 64 cols) ============
    ln_vec(g_hbuf[0], lnf_g, lnf_b, sm, sm + 1024, sm + 2048, tid);
    float lastv = sm[tid];
    if (bid == 0) {
        out[2 * (size_t)KS_ELEMS] = (float)TKV;                 // kv_len
        out[2 * (size_t)KS_ELEMS + 1 + tid] = lastv;            // last
    }
    {
        int cb = bid * 64;
        if (cb < VOC) {
            int c = tid & 63, dg = tid >> 6;
            int col = cb + c;
            float acc = 0.0f;
            if (col < VOC) {
                for (int d = dg; d < DM; d += 16)
                    acc += sm[d] * __ldg(&lm_w[(size_t)d * VOC + col]);
            }
            float* sacc = sm + 1024;
            sacc[dg * 64 + c] = acc;
            for (int s = 8; s > 0; s >>= 1) {
                __syncthreads();
                if (dg < s) sacc[dg * 64 + c] += sacc[(dg + s) * 64 + c];
            }
            __syncthreads();
            if (dg == 0 && col < VOC) {
                float logit = sacc[c] * __ldg(&logits_scale[col]);
                unsigned u = __float_as_uint(logit);
                u = (u & 0x80000000u) ? ~u : (u | 0x80000000u);
                unsigned long long key =
                    ((unsigned long long)u << 32) |
                    (unsigned long long)(0xFFFFFFFFu - (unsigned)col);
                atomicMax(&g_best, key);
            }
        }
    }
    gbar();

    if (bid == 0 && tid == 0) {
        unsigned long long b = atomicMax(&g_best, 0ull);
        unsigned col = 0xFFFFFFFFu - (unsigned)(b & 0xFFFFFFFFull);
        out[2 * (size_t)KS_ELEMS + 1 + DM] = (float)col;        // max_ids
    }
}

extern "C" void kernel_launch(void* const* d_in, const int* in_sizes, int n_in,
                              void* d_out, int out_size) {
    const float* past_k       = (const float*)d_in[0];
    const float* past_v       = (const float*)d_in[1];
    const float* hidden       = (const float*)d_in[2];
    const float* logits_scale = (const float*)d_in[3];
    const float* mask_scale   = (const float*)d_in[4];
    const float* ln1_g        = (const float*)d_in[5];
    const float* ln1_b        = (const float*)d_in[6];
    const float* Wq           = (const float*)d_in[7];
    const float* bq           = (const float*)d_in[8];
    const float* Wk           = (const float*)d_in[9];
    const float* bk           = (const float*)d_in[10];
    const float* Wv           = (const float*)d_in[11];
    const float* bv           = (const float*)d_in[12];
    const float* Wo           = (const float*)d_in[13];
    const float* bo           = (const float*)d_in[14];
    const float* ln2_g        = (const float*)d_in[15];
    const float* ln2_b        = (const float*)d_in[16];
    const float* Wfc          = (const float*)d_in[17];
    const float* bfc          = (const float*)d_in[18];
    const float* Wmp          = (const float*)d_in[19];
    const float* bmp          = (const float*)d_in[20];
    const float* lnf_g        = (const float*)d_in[21];
    const float* lnf_b        = (const float*)d_in[22];
    const float* lm_w         = (const float*)d_in[23];
    float* outp = (float*)d_out;

    tts_decode_kernel<<<NB, NT>>>(past_k, past_v, hidden, logits_scale, mask_scale,
                                  ln1_g, ln1_b, Wq, bq, Wk, bk, Wv, bv, Wo, bo,
                                  ln2_g, ln2_b, Wfc, bfc, Wmp, bmp,
                                  lnf_g, lnf_b, lm_w, outp);
}